// round 2
// baseline (speedup 1.0000x reference)
#include <cuda_runtime.h>
#include <cstdint>

// Problem constants (shapes fixed by the dataset).
#define NN 100000
#define EE 1600000
#define RR 8
#define DD 128

// Scratch (device globals: no allocation allowed). 16B-aligned for float4/red.v4.
__device__ __align__(16) float g_xr[(size_t)NN * DD];    // per-relation transformed feats
__device__ __align__(16) float g_h [(size_t)NN * DD];    // hidden activations
__device__ __align__(16) float g_norm[(size_t)NN * RR];  // 1/cnt per (dst, rel)
__device__ int g_shift;  // 1 if edge arrays are int64 (stride-2 int words), 0 if int32

// ---------------------------------------------------------------------------
// Detect int64 vs int32 edge arrays: int64 => all odd 32-bit words are 0.
// edge_type values are in [0,8) so for int32 data odd words are ~uniform [0,8):
// 2048 odd samples all zero has probability ~8^-2048. Deterministic.
// ---------------------------------------------------------------------------
__global__ void detect_k(const int* __restrict__ et, int E) {
    __shared__ int any;
    if (threadIdx.x == 0) any = 0;
    __syncthreads();
    int n = min(E, 4096);
    int local = 0;
    for (int i = threadIdx.x; i < n; i += blockDim.x)
        local |= et[2 * i + 1];
    if (local) atomicOr(&any, 1);
    __syncthreads();
    if (threadIdx.x == 0) g_shift = any ? 0 : 1;
}

// ---------------------------------------------------------------------------
// Small utility kernels
// ---------------------------------------------------------------------------
__global__ void zero_norm_k(float* norm, int n) {
    int i = blockIdx.x * blockDim.x + threadIdx.x;
    if (i < n) norm[i] = 0.0f;
}

__global__ void hist_k(const int* __restrict__ ei, const int* __restrict__ et,
                       float* __restrict__ norm, int E) {
    int e = blockIdx.x * blockDim.x + threadIdx.x;
    if (e < E) {
        const int sh = g_shift;
        int d = ei[(E << sh) + (e << sh)];
        int r = et[e << sh];
        if ((unsigned)d < NN && (unsigned)r < RR)
            atomicAdd(&norm[d * RR + r], 1.0f);
    }
}

__global__ void invert_k(float* __restrict__ norm, int n) {
    int i = blockIdx.x * blockDim.x + threadIdx.x;
    if (i < n) {
        float v = norm[i];
        norm[i] = (v > 0.0f) ? (1.0f / v) : 0.0f;
    }
}

__global__ void relu_k(float* __restrict__ a, size_t n) {
    size_t i = (size_t)blockIdx.x * blockDim.x + threadIdx.x;
    if (i < n) a[i] = fmaxf(a[i], 0.0f);
}

// ---------------------------------------------------------------------------
// SGEMM: C[M,128] = A[M,128] * B[128,128] (+ bias). Block tile 128x128, K=128
// resident in smem, 256 threads, 8x8 microtile per thread.
// ---------------------------------------------------------------------------
#define AS_STRIDE 129
#define SGEMM_SMEM ((128 * AS_STRIDE + 128 * 128) * 4)

__global__ void __launch_bounds__(256, 1)
sgemm128_k(const float* __restrict__ A, const float* __restrict__ B,
           const float* __restrict__ bias, float* __restrict__ C, int M) {
    extern __shared__ float sm[];
    float* As = sm;                    // [128][AS_STRIDE]  (m x k)
    float* Bs = sm + 128 * AS_STRIDE;  // [128][128]        (k x n)

    const int t  = threadIdx.x;
    const int m0 = blockIdx.x * 128;

    {
        const int k4 = (t & 31) * 4;
        const int mr = t >> 5;
#pragma unroll
        for (int i = 0; i < 16; i++) {
            const int m  = mr + i * 8;
            const int gm = m0 + m;
            float4 v = make_float4(0.f, 0.f, 0.f, 0.f);
            if (gm < M) v = *(const float4*)(A + (size_t)gm * DD + k4);
            float* p = As + m * AS_STRIDE + k4;
            p[0] = v.x; p[1] = v.y; p[2] = v.z; p[3] = v.w;
        }
        const int n4 = (t & 31) * 4;
        const int kr = t >> 5;
#pragma unroll
        for (int i = 0; i < 16; i++) {
            const int k = kr + i * 8;
            *(float4*)(Bs + k * 128 + n4) = *(const float4*)(B + k * 128 + n4);
        }
    }
    __syncthreads();

    const int tx = t & 15;  // n
    const int ty = t >> 4;  // m

    float acc[8][8];
#pragma unroll
    for (int i = 0; i < 8; i++)
#pragma unroll
        for (int j = 0; j < 8; j++) acc[i][j] = 0.0f;

#pragma unroll 4
    for (int k = 0; k < 128; k++) {
        float a[8], b[8];
#pragma unroll
        for (int i = 0; i < 8; i++) a[i] = As[(ty * 8 + i) * AS_STRIDE + k];
        float4 b0 = *(const float4*)(Bs + k * 128 + tx * 8);
        float4 b1 = *(const float4*)(Bs + k * 128 + tx * 8 + 4);
        b[0] = b0.x; b[1] = b0.y; b[2] = b0.z; b[3] = b0.w;
        b[4] = b1.x; b[5] = b1.y; b[6] = b1.z; b[7] = b1.w;
#pragma unroll
        for (int i = 0; i < 8; i++)
#pragma unroll
            for (int j = 0; j < 8; j++) acc[i][j] += a[i] * b[j];
    }

    float bv[8];
    if (bias != nullptr) {
#pragma unroll
        for (int j = 0; j < 8; j++) bv[j] = bias[tx * 8 + j];
    } else {
#pragma unroll
        for (int j = 0; j < 8; j++) bv[j] = 0.0f;
    }
#pragma unroll
    for (int i = 0; i < 8; i++) {
        const int gm = m0 + ty * 8 + i;
        if (gm < M) {
            float4 v0 = make_float4(acc[i][0] + bv[0], acc[i][1] + bv[1],
                                    acc[i][2] + bv[2], acc[i][3] + bv[3]);
            float4 v1 = make_float4(acc[i][4] + bv[4], acc[i][5] + bv[5],
                                    acc[i][6] + bv[6], acc[i][7] + bv[7]);
            *(float4*)(C + (size_t)gm * DD + tx * 8)     = v0;
            *(float4*)(C + (size_t)gm * DD + tx * 8 + 4) = v1;
        }
    }
}

// ---------------------------------------------------------------------------
// Edge scatter pass for one relation: out[dst] += xr[src] * norm[dst, r]
// One warp per matching edge (32 lanes x float4 = 512B row). xr and out are
// both L2-resident (51MB each) during the pass.
// ---------------------------------------------------------------------------
__global__ void edge_pass_k(const int* __restrict__ ei, const int* __restrict__ et,
                            const float* __restrict__ norm, const float* __restrict__ msg,
                            float* __restrict__ out, int E, int r) {
    const int sh   = g_shift;
    const int lane = threadIdx.x & 31;
    const int gw   = (blockIdx.x * blockDim.x + threadIdx.x) >> 5;
    const int nw   = (gridDim.x * blockDim.x) >> 5;

    for (int base = gw * 32; base < E; base += nw * 32) {
        const int e = base + lane;
        const bool match = (e < E) && (et[e << sh] == r);
        unsigned mask = __ballot_sync(0xffffffffu, match);
        while (mask) {
            const int b = __ffs(mask) - 1;
            mask &= mask - 1;
            const int ee = base + b;
            const int s  = ei[ee << sh];                 // src (broadcast load)
            const int d  = ei[(E << sh) + (ee << sh)];   // dst
            if ((unsigned)s >= NN || (unsigned)d >= NN) continue;
            const float nr = norm[d * RR + r];
            const float4 v = *(const float4*)(msg + (size_t)s * DD + lane * 4);
            float* p = out + (size_t)d * DD + lane * 4;
            asm volatile("red.global.add.v4.f32 [%0], {%1,%2,%3,%4};"
                         :: "l"(p), "f"(v.x * nr), "f"(v.y * nr),
                            "f"(v.z * nr), "f"(v.w * nr)
                         : "memory");
        }
    }
}

// ---------------------------------------------------------------------------
// Launch
// ---------------------------------------------------------------------------
extern "C" void kernel_launch(void* const* d_in, const int* in_sizes, int n_in,
                              void* d_out, int out_size) {
    const float* x     = (const float*)d_in[0];
    const int*   ei    = (const int*)d_in[1];   // [2,E] int64 OR int32 (autodetected)
    const int*   et    = (const int*)d_in[2];   // [E]   int64 OR int32
    const float* W1    = (const float*)d_in[3];
    const float* root1 = (const float*)d_in[4];
    const float* b1    = (const float*)d_in[5];
    const float* W2    = (const float*)d_in[6];
    const float* root2 = (const float*)d_in[7];
    const float* b2    = (const float*)d_in[8];
    float* out = (float*)d_out;

    const int E = in_sizes[1] / 2;   // 2E elements under both dtype interpretations
    const int N = in_sizes[0] / DD;

    float *xr, *h, *norm;
    cudaGetSymbolAddress((void**)&xr,   g_xr);
    cudaGetSymbolAddress((void**)&h,    g_h);
    cudaGetSymbolAddress((void**)&norm, g_norm);

    cudaFuncSetAttribute(sgemm128_k, cudaFuncAttributeMaxDynamicSharedMemorySize,
                         SGEMM_SMEM);

    const int gemm_grid = (N + 127) / 128;
    const int edge_grid = 148 * 8;
    const int NR = N * RR;

    detect_k<<<1, 256>>>(et, E);

    // Degree normalization table (shared by both layers)
    zero_norm_k<<<(NR + 255) / 256, 256>>>(norm, NR);
    hist_k<<<(E + 255) / 256, 256>>>(ei, et, norm, E);
    invert_k<<<(NR + 255) / 256, 256>>>(norm, NR);

    // Layer 1: h = x@root1 + b1 + sum_r scatter(mean_r(x@W1r))
    sgemm128_k<<<gemm_grid, 256, SGEMM_SMEM>>>(x, root1, b1, h, N);
    for (int r = 0; r < RR; r++) {
        sgemm128_k<<<gemm_grid, 256, SGEMM_SMEM>>>(x, W1 + (size_t)r * DD * DD,
                                                   nullptr, xr, N);
        edge_pass_k<<<edge_grid, 256>>>(ei, et, norm, xr, h, E, r);
    }
    relu_k<<<((size_t)N * DD + 255) / 256, 256>>>(h, (size_t)N * DD);

    // Layer 2 into d_out
    sgemm128_k<<<gemm_grid, 256, SGEMM_SMEM>>>(h, root2, b2, out, N);
    for (int r = 0; r < RR; r++) {
        sgemm128_k<<<gemm_grid, 256, SGEMM_SMEM>>>(h, W2 + (size_t)r * DD * DD,
                                                   nullptr, xr, N);
        edge_pass_k<<<edge_grid, 256>>>(ei, et, norm, xr, out, E, r);
    }
}

// round 5
// speedup vs baseline: 1.5815x; 1.5815x over previous
#include <cuda_runtime.h>
#include <cuda_bf16.h>
#include <cstdint>

// Problem constants (shapes fixed by the dataset).
#define NN 100000
#define EE 1600000
#define RR 8
#define DD 128

// ---------------------------------------------------------------------------
// Scratch (device globals; no allocation allowed anywhere).
// ---------------------------------------------------------------------------
__device__ __align__(16) float g_xr[(size_t)NN * DD];     // per-relation transformed feats
__device__ __align__(16) float g_h [(size_t)NN * DD];     // hidden activations
__device__ __align__(16) float g_norm[(size_t)NN * RR];   // 1/cnt per (dst, rel)
__device__ __align__(16) __nv_bfloat16 g_ah[(size_t)NN * DD];  // bf16 high part of A
__device__ __align__(16) __nv_bfloat16 g_al[(size_t)NN * DD];  // bf16 residual of A
__device__ __align__(16) __nv_bfloat16 g_wh[9 * DD * DD];      // [n][k] weights, high
__device__ __align__(16) __nv_bfloat16 g_wl[9 * DD * DD];      // [n][k] weights, resid
__device__ int g_shift;  // 1 if edge arrays are int64 (stride-2 words), 0 if int32

// ---------------------------------------------------------------------------
// dtype autodetect (int64 edges => all odd 32-bit words zero)
// ---------------------------------------------------------------------------
__global__ void detect_k(const int* __restrict__ et, int E) {
    __shared__ int any;
    if (threadIdx.x == 0) any = 0;
    __syncthreads();
    int n = min(E, 4096);
    int local = 0;
    for (int i = threadIdx.x; i < n; i += blockDim.x) local |= et[2 * i + 1];
    if (local) atomicOr(&any, 1);
    __syncthreads();
    if (threadIdx.x == 0) g_shift = any ? 0 : 1;
}

// ---------------------------------------------------------------------------
// Utility kernels
// ---------------------------------------------------------------------------
__global__ void zero_norm_k(float* norm, int n) {
    int i = blockIdx.x * blockDim.x + threadIdx.x;
    if (i < n) norm[i] = 0.0f;
}
__global__ void hist_k(const int* __restrict__ ei, const int* __restrict__ et,
                       float* __restrict__ norm, int E) {
    int e = blockIdx.x * blockDim.x + threadIdx.x;
    if (e < E) {
        const int sh = g_shift;
        int d = ei[(E << sh) + (e << sh)];
        int r = et[e << sh];
        if ((unsigned)d < NN && (unsigned)r < RR)
            atomicAdd(&norm[d * RR + r], 1.0f);
    }
}
__global__ void invert_k(float* __restrict__ norm, int n) {
    int i = blockIdx.x * blockDim.x + threadIdx.x;
    if (i < n) {
        float v = norm[i];
        norm[i] = (v > 0.0f) ? (1.0f / v) : 0.0f;
    }
}
__global__ void relu_k(float* __restrict__ a, size_t n) {
    size_t i = (size_t)blockIdx.x * blockDim.x + threadIdx.x;
    if (i < n) a[i] = fmaxf(a[i], 0.0f);
}

// Split fp32 -> bf16 hi + bf16 residual (vectorized, n4 = count/4)
__global__ void split_k(const float* __restrict__ A, __nv_bfloat16* __restrict__ H,
                        __nv_bfloat16* __restrict__ L, size_t n4) {
    size_t i = (size_t)blockIdx.x * blockDim.x + threadIdx.x;
    if (i < n4) {
        float4 v = ((const float4*)A)[i];
        __nv_bfloat162 h0 = __floats2bfloat162_rn(v.x, v.y);
        __nv_bfloat162 h1 = __floats2bfloat162_rn(v.z, v.w);
        __nv_bfloat162 l0 = __floats2bfloat162_rn(v.x - __bfloat162float(h0.x),
                                                  v.y - __bfloat162float(h0.y));
        __nv_bfloat162 l1 = __floats2bfloat162_rn(v.z - __bfloat162float(h1.x),
                                                  v.w - __bfloat162float(h1.y));
        ((__nv_bfloat162*)H)[2 * i]     = h0;
        ((__nv_bfloat162*)H)[2 * i + 1] = h1;
        ((__nv_bfloat162*)L)[2 * i]     = l0;
        ((__nv_bfloat162*)L)[2 * i + 1] = l1;
    }
}

// Transpose + split weights: out[m][n][k] = split(W[m][k][n])
__global__ void splitw_k(const float* __restrict__ W, __nv_bfloat16* __restrict__ H,
                         __nv_bfloat16* __restrict__ L, int nmat) {
    int idx = blockIdx.x * blockDim.x + threadIdx.x;
    int total = nmat * DD * DD;
    if (idx < total) {
        int m = idx >> 14;
        int rem = idx & 16383;
        int n = rem >> 7;
        int k = rem & 127;
        float v = W[(m << 14) + (k << 7) + n];
        __nv_bfloat16 h = __float2bfloat16(v);
        __nv_bfloat16 l = __float2bfloat16(v - __bfloat162float(h));
        H[idx] = h;
        L[idx] = l;
    }
}

// ---------------------------------------------------------------------------
// Tensor-core GEMM via mma.sync (portable PTX, no 'a'-gated features).
// C[M,128] = A[M,128] @ W[128,128] (+bias), split-bf16 in 3 passes:
//   AhBh + AlBh + AhBl   (AlBl dropped, ~4e-6 rel)
// 256 threads / 8 warps; block tile 128x128; K=128 fully smem-resident.
// B is [n][k] so non-trans ldmatrix.x4 matches the b-fragment layout.
// ---------------------------------------------------------------------------
#define SSTR 136                         // padded smem stride (bf16 elems)
#define TILE_BYTES (128 * SSTR * 2)      // 34816
#define GSMEM (4 * TILE_BYTES)           // Ah, Al, Bh, Bl

static __device__ __forceinline__ uint32_t smem_u32(const void* p) {
    uint32_t a;
    asm("{ .reg .u64 t; cvta.to.shared.u64 t, %1; cvt.u32.u64 %0, t; }"
        : "=r"(a) : "l"(p));
    return a;
}
#define LDSM_X4(r0, r1, r2, r3, addr) \
    asm volatile("ldmatrix.sync.aligned.m8n8.x4.shared.b16 {%0,%1,%2,%3}, [%4];" \
                 : "=r"(r0), "=r"(r1), "=r"(r2), "=r"(r3) : "r"(addr))
#define MMA16816(d, a, b0, b1) \
    asm volatile("mma.sync.aligned.m16n8k16.row.col.f32.bf16.bf16.f32 " \
                 "{%0,%1,%2,%3}, {%4,%5,%6,%7}, {%8,%9}, {%0,%1,%2,%3};" \
                 : "+f"((d)[0]), "+f"((d)[1]), "+f"((d)[2]), "+f"((d)[3]) \
                 : "r"((a)[0]), "r"((a)[1]), "r"((a)[2]), "r"((a)[3]), \
                   "r"(b0), "r"(b1))

__global__ void __launch_bounds__(256, 1)
gemm_tc_k(const __nv_bfloat16* __restrict__ Ah, const __nv_bfloat16* __restrict__ Al,
          const __nv_bfloat16* __restrict__ Bh, const __nv_bfloat16* __restrict__ Bl,
          const float* __restrict__ bias, float* __restrict__ C, int M) {
    extern __shared__ char smc[];
    __nv_bfloat16* sAh = (__nv_bfloat16*)smc;
    __nv_bfloat16* sAl = (__nv_bfloat16*)(smc + TILE_BYTES);
    __nv_bfloat16* sBh = (__nv_bfloat16*)(smc + 2 * TILE_BYTES);
    __nv_bfloat16* sBl = (__nv_bfloat16*)(smc + 3 * TILE_BYTES);

    const int t   = threadIdx.x;
    const int wid = t >> 5, lid = t & 31;
    const int m0  = blockIdx.x * 128;

    // ---- Load tiles. Each 128-bf16 row = 256B = 16 uint4 chunks.
    // 128 rows x 16 chunks = 2048 chunks per tile, 256 threads -> 8 iters.
#pragma unroll
    for (int it = 0; it < 8; it++) {
        const int idx = it * 256 + t;
        const int row = idx >> 4;                // 0..127
        const int c16 = (idx & 15) * 8;          // bf16 col of this 16B chunk
        const int soff = row * SSTR + c16;
        // B (always full 128 rows)
        *(uint4*)(sBh + soff) = *(const uint4*)(Bh + row * DD + c16);
        *(uint4*)(sBl + soff) = *(const uint4*)(Bl + row * DD + c16);
        // A (guard rows)
        uint4 vh = make_uint4(0, 0, 0, 0), vl = make_uint4(0, 0, 0, 0);
        const int gr = m0 + row;
        if (gr < M) {
            vh = *(const uint4*)(Ah + (size_t)gr * DD + c16);
            vl = *(const uint4*)(Al + (size_t)gr * DD + c16);
        }
        *(uint4*)(sAh + soff) = vh;
        *(uint4*)(sAl + soff) = vl;
    }
    __syncthreads();

    // Warp layout: 4 (m) x 2 (n); warp tile 32(m) x 64(n)
    const int warpM = (wid & 3) * 32;
    const int warpN = (wid >> 2) * 64;

    float acc[2][8][4];
#pragma unroll
    for (int i = 0; i < 2; i++)
#pragma unroll
        for (int j = 0; j < 8; j++)
#pragma unroll
            for (int c = 0; c < 4; c++) acc[i][j][c] = 0.0f;

    // ldmatrix lane addressing (element indices within the tile)
    const int aRow = warpM + (lid & 15);             // + mi*16
    const int aK   = (lid >> 4) << 3;                // + k0
    const int bN   = warpN + (lid & 7) + ((lid >> 4) << 3);  // + bq*16
    const int bK   = ((lid >> 3) & 1) << 3;          // + k0

    const uint32_t uAh = smem_u32(sAh), uAl = smem_u32(sAl);
    const uint32_t uBh = smem_u32(sBh), uBl = smem_u32(sBl);

#pragma unroll
    for (int pass = 0; pass < 3; pass++) {
        const uint32_t ua = (pass == 1) ? uAl : uAh;
        const uint32_t ub = (pass == 2) ? uBl : uBh;
#pragma unroll
        for (int k0 = 0; k0 < 128; k0 += 16) {
            uint32_t a[2][4];
#pragma unroll
            for (int mi = 0; mi < 2; mi++) {
                const uint32_t addr = ua + (uint32_t)(((aRow + mi * 16) * SSTR
                                                       + (aK + k0)) * 2);
                LDSM_X4(a[mi][0], a[mi][1], a[mi][2], a[mi][3], addr);
            }
            uint32_t b[4][4];
#pragma unroll
            for (int bq = 0; bq < 4; bq++) {
                const uint32_t addr = ub + (uint32_t)(((bN + bq * 16) * SSTR
                                                       + (bK + k0)) * 2);
                LDSM_X4(b[bq][0], b[bq][1], b[bq][2], b[bq][3], addr);
            }
#pragma unroll
            for (int mi = 0; mi < 2; mi++)
#pragma unroll
                for (int nj = 0; nj < 8; nj++) {
                    const int bq = nj >> 1, hi = (nj & 1) << 1;
                    MMA16816(acc[mi][nj], a[mi], b[bq][hi], b[bq][hi + 1]);
                }
        }
    }

    // ---- Epilogue ----
    const int g  = lid >> 2;       // row within fragment
    const int tg = lid & 3;        // col pair
#pragma unroll
    for (int mi = 0; mi < 2; mi++) {
#pragma unroll
        for (int nj = 0; nj < 8; nj++) {
            const int col = warpN + nj * 8 + tg * 2;
            float bx = 0.f, by = 0.f;
            if (bias) { bx = bias[col]; by = bias[col + 1]; }
            const int r0 = m0 + warpM + mi * 16 + g;
            const int r1 = r0 + 8;
            if (r0 < M) {
                float2 v = make_float2(acc[mi][nj][0] + bx, acc[mi][nj][1] + by);
                *(float2*)(C + (size_t)r0 * DD + col) = v;
            }
            if (r1 < M) {
                float2 v = make_float2(acc[mi][nj][2] + bx, acc[mi][nj][3] + by);
                *(float2*)(C + (size_t)r1 * DD + col) = v;
            }
        }
    }
}

// ---------------------------------------------------------------------------
// Edge scatter pass for one relation: out[dst] += xr[src] * norm[dst, r]
// ---------------------------------------------------------------------------
__global__ void edge_pass_k(const int* __restrict__ ei, const int* __restrict__ et,
                            const float* __restrict__ norm, const float* __restrict__ msg,
                            float* __restrict__ out, int E, int r) {
    const int sh   = g_shift;
    const int lane = threadIdx.x & 31;
    const int gw   = (blockIdx.x * blockDim.x + threadIdx.x) >> 5;
    const int nw   = (gridDim.x * blockDim.x) >> 5;

    for (int base = gw * 32; base < E; base += nw * 32) {
        const int e = base + lane;
        const bool match = (e < E) && (et[e << sh] == r);
        unsigned mask = __ballot_sync(0xffffffffu, match);
        while (mask) {
            const int b = __ffs(mask) - 1;
            mask &= mask - 1;
            const int ee = base + b;
            const int s  = ei[ee << sh];
            const int d  = ei[(E << sh) + (ee << sh)];
            if ((unsigned)s >= NN || (unsigned)d >= NN) continue;
            const float nr = norm[d * RR + r];
            const float4 v = *(const float4*)(msg + (size_t)s * DD + lane * 4);
            float* p = out + (size_t)d * DD + lane * 4;
            asm volatile("red.global.add.v4.f32 [%0], {%1,%2,%3,%4};"
                         :: "l"(p), "f"(v.x * nr), "f"(v.y * nr),
                            "f"(v.z * nr), "f"(v.w * nr)
                         : "memory");
        }
    }
}

// ---------------------------------------------------------------------------
// Launch
// ---------------------------------------------------------------------------
extern "C" void kernel_launch(void* const* d_in, const int* in_sizes, int n_in,
                              void* d_out, int out_size) {
    const float* x     = (const float*)d_in[0];
    const int*   ei    = (const int*)d_in[1];
    const int*   et    = (const int*)d_in[2];
    const float* W1    = (const float*)d_in[3];
    const float* root1 = (const float*)d_in[4];
    const float* b1    = (const float*)d_in[5];
    const float* W2    = (const float*)d_in[6];
    const float* root2 = (const float*)d_in[7];
    const float* b2    = (const float*)d_in[8];
    float* out = (float*)d_out;

    const int E = in_sizes[1] / 2;
    const int N = in_sizes[0] / DD;

    float *xr, *h, *norm;
    __nv_bfloat16 *ah, *al, *wh, *wl;
    cudaGetSymbolAddress((void**)&xr,   g_xr);
    cudaGetSymbolAddress((void**)&h,    g_h);
    cudaGetSymbolAddress((void**)&norm, g_norm);
    cudaGetSymbolAddress((void**)&ah,   g_ah);
    cudaGetSymbolAddress((void**)&al,   g_al);
    cudaGetSymbolAddress((void**)&wh,   g_wh);
    cudaGetSymbolAddress((void**)&wl,   g_wl);

    cudaFuncSetAttribute(gemm_tc_k, cudaFuncAttributeMaxDynamicSharedMemorySize, GSMEM);

    const int gemm_grid = (N + 127) / 128;
    const int edge_grid = 148 * 8;
    const int NR = N * RR;
    const size_t n4 = (size_t)N * DD / 4;

    detect_k<<<1, 256>>>(et, E);
    zero_norm_k<<<(NR + 255) / 256, 256>>>(norm, NR);
    hist_k<<<(E + 255) / 256, 256>>>(ei, et, norm, E);
    invert_k<<<(NR + 255) / 256, 256>>>(norm, NR);

    // ---- Layer 1 ----
    split_k<<<(int)((n4 + 255) / 256), 256>>>(x, ah, al, n4);
    splitw_k<<<(DD * DD + 255) / 256, 256>>>(root1, wh, wl, 1);
    splitw_k<<<(RR * DD * DD + 255) / 256, 256>>>(W1, wh + DD * DD, wl + DD * DD, RR);

    gemm_tc_k<<<gemm_grid, 256, GSMEM>>>(ah, al, wh, wl, b1, h, N);
    for (int r = 0; r < RR; r++) {
        gemm_tc_k<<<gemm_grid, 256, GSMEM>>>(ah, al, wh + (size_t)(r + 1) * DD * DD,
                                             wl + (size_t)(r + 1) * DD * DD, nullptr, xr, N);
        edge_pass_k<<<edge_grid, 256>>>(ei, et, norm, xr, h, E, r);
    }
    relu_k<<<(int)(((size_t)N * DD + 255) / 256), 256>>>(h, (size_t)N * DD);

    // ---- Layer 2 ----
    split_k<<<(int)((n4 + 255) / 256), 256>>>(h, ah, al, n4);
    splitw_k<<<(DD * DD + 255) / 256, 256>>>(root2, wh, wl, 1);
    splitw_k<<<(RR * DD * DD + 255) / 256, 256>>>(W2, wh + DD * DD, wl + DD * DD, RR);

    gemm_tc_k<<<gemm_grid, 256, GSMEM>>>(ah, al, wh, wl, b2, out, N);
    for (int r = 0; r < RR; r++) {
        gemm_tc_k<<<gemm_grid, 256, GSMEM>>>(ah, al, wh + (size_t)(r + 1) * DD * DD,
                                             wl + (size_t)(r + 1) * DD * DD, nullptr, xr, N);
        edge_pass_k<<<edge_grid, 256>>>(ei, et, norm, xr, out, E, r);
    }
}